// round 14
// baseline (speedup 1.0000x reference)
#include <cuda_runtime.h>

// ReLU_Conv (CROWN-style ReLU relaxation over bound maps)
// Round 14: R13 (Blackwell 256-bit LDG/STG.E.256, 1 neuron per 128-thread
//           block, single barrier, redundant finalize) at residency 13
//           blocks/SM — probing the top of the measured warp-residency
//           curve (peak ~44-48 warps/SM). The v8 front batch (2 indivisible
//           instructions) is immune to the reordering that broke the f4
//           variants at tight register budgets.
// Output layout: [lx_out | ux_out | lc_out | uc_out]

__device__ __forceinline__ void ld_cs_v8(const float* p, float v[8]) {
    asm volatile("ld.global.cs.v8.f32 {%0,%1,%2,%3,%4,%5,%6,%7}, [%8];"
                 : "=f"(v[0]), "=f"(v[1]), "=f"(v[2]), "=f"(v[3]),
                   "=f"(v[4]), "=f"(v[5]), "=f"(v[6]), "=f"(v[7])
                 : "l"(p));
}

__device__ __forceinline__ void ld_nc_v8(const float* p, float v[8]) {
    asm volatile("ld.global.nc.v8.f32 {%0,%1,%2,%3,%4,%5,%6,%7}, [%8];"
                 : "=f"(v[0]), "=f"(v[1]), "=f"(v[2]), "=f"(v[3]),
                   "=f"(v[4]), "=f"(v[5]), "=f"(v[6]), "=f"(v[7])
                 : "l"(p));
}

__device__ __forceinline__ void st_cs_v8(float* p, const float v[8]) {
    asm volatile("st.global.cs.v8.f32 [%0], {%1,%2,%3,%4,%5,%6,%7,%8};"
                 :: "l"(p),
                    "f"(v[0]), "f"(v[1]), "f"(v[2]), "f"(v[3]),
                    "f"(v[4]), "f"(v[5]), "f"(v[6]), "f"(v[7])
                 : "memory");
}

__global__ __launch_bounds__(128, 13)
void relu_conv_kernel(
    const float* __restrict__ lx, const float* __restrict__ ux,
    const float* __restrict__ lc, const float* __restrict__ uc,
    const float* __restrict__ xmin, const float* __restrict__ xmax,
    float* __restrict__ lx_out, float* __restrict__ ux_out,
    float* __restrict__ lc_out, float* __restrict__ uc_out)
{
    const int tid = threadIdx.x;                       // 0..127
    const int n   = blockIdx.x;                        // this block's neuron
    const size_t base = (size_t)n * 1024 + (size_t)tid * 8;

    // Front batch: two 256-bit streaming loads (32B-aligned).
    float vlx[8], vux[8];
    ld_cs_v8(lx + base, vlx);
    ld_cs_v8(ux + base, vux);
    const float lcv = __ldg(lc + n);
    const float ucv = __ldg(uc + n);

    // Broadcast bounds (8 KB total, L1/L2 resident after wave 1).
    float vmn[8], vmx[8];
    ld_nc_v8(xmin + (size_t)tid * 8, vmn);
    ld_nc_v8(xmax + (size_t)tid * 8, vmx);

    // Accumulate. (l>0 ? mn : (l<0 ? mx : 0)) * l == (l>0 ? mn : mx) * l
    // for finite bounds (the l==0 branch multiplies to zero either way).
    float sl = 0.f, su = 0.f;
    #pragma unroll
    for (int i = 0; i < 8; i++) {
        sl += (vlx[i] > 0.f ? vmn[i] : vmx[i]) * vlx[i];
        su += (vux[i] > 0.f ? vmx[i] : vmn[i]) * vux[i];
    }

    // Warp reduction.
    #pragma unroll
    for (int off = 16; off; off >>= 1) {
        sl += __shfl_down_sync(0xffffffffu, sl, off);
        su += __shfl_down_sync(0xffffffffu, su, off);
    }

    __shared__ float2 sPart[4];                        // per-warp partials
    const int warp = tid >> 5, lane = tid & 31;
    if (lane == 0) sPart[warp] = make_float2(sl, su);
    __syncthreads();                                   // the ONLY barrier

    // Every thread redundantly finalizes (broadcast smem reads).
    const float2 p0 = sPart[0], p1 = sPart[1], p2 = sPart[2], p3 = sPart[3];
    const float l = (p0.x + p1.x) + (p2.x + p3.x) + lcv;
    const float u = (p0.y + p1.y) + (p2.y + p3.y) + ucv;

    const bool alive = (l >= 0.f);
    const bool cross = (l < 0.f) && (u > 0.f);
    float slope = cross ? (u / (u - l)) : 1.f;
    slope = fminf(fmaxf(slope, 0.f), 1.f);

    // Per-neuron epilogue multipliers (identical values to the reference
    // selects; 0*finite stores +/-0 which is exact under rel-err).
    const float mlx = alive ? 1.f : 0.f;
    const float mux = alive ? 1.f : (cross ? slope : 0.f);

    if (tid == 0) {
        lc_out[n] = alive ? lcv : 0.f;
        uc_out[n] = alive ? ucv : (cross ? (slope * ucv - slope * l) : 0.f);
    }

    float olx[8], oux[8];
    #pragma unroll
    for (int i = 0; i < 8; i++) {
        olx[i] = mlx * vlx[i];
        oux[i] = mux * vux[i];
    }
    st_cs_v8(lx_out + base, olx);
    st_cs_v8(ux_out + base, oux);
}

extern "C" void kernel_launch(void* const* d_in, const int* in_sizes, int n_in,
                              void* d_out, int out_size)
{
    const float* lx   = (const float*)d_in[0];
    const float* ux   = (const float*)d_in[1];
    const float* lc   = (const float*)d_in[2];
    const float* uc   = (const float*)d_in[3];
    const float* xmin = (const float*)d_in[4];
    const float* xmax = (const float*)d_in[5];

    const int neurons = in_sizes[2];          // C*H*W = 32768
    const size_t nel  = (size_t)neurons * 1024;

    float* out    = (float*)d_out;
    float* lx_out = out;
    float* ux_out = out + nel;
    float* lc_out = out + 2 * nel;
    float* uc_out = out + 2 * nel + neurons;

    relu_conv_kernel<<<neurons, 128>>>(lx, ux, lc, uc, xmin, xmax,
                                       lx_out, ux_out, lc_out, uc_out);
}

// round 15
// speedup vs baseline: 1.0467x; 1.0467x over previous
#include <cuda_runtime.h>

// ReLU_Conv (CROWN-style ReLU relaxation over bound maps) — FINAL (== R13)
// Measured optimum over 14 variants on GB300:
//   1 neuron per 128-thread block; Blackwell 256-bit vector memory ops
//   (LDG.E.256 / STG.E.256): each thread owns 8 consecutive floats of the
//   row -> 2-instruction front batch of streaming loads, 2 vector stores.
//   occ 12 / 40-reg allocator mode (occ>=13 spills: DRAM 80.3% -> 75.8%),
//   single 4-warp barrier, redundant per-thread finalize.
//   Session evidence: ~6.36 TB/s (80% of spec HBM) is the architectural
//   ceiling for this fused 1:1 read/write stream.
// Output layout: [lx_out | ux_out | lc_out | uc_out]

__device__ __forceinline__ void ld_cs_v8(const float* p, float v[8]) {
    asm volatile("ld.global.cs.v8.f32 {%0,%1,%2,%3,%4,%5,%6,%7}, [%8];"
                 : "=f"(v[0]), "=f"(v[1]), "=f"(v[2]), "=f"(v[3]),
                   "=f"(v[4]), "=f"(v[5]), "=f"(v[6]), "=f"(v[7])
                 : "l"(p));
}

__device__ __forceinline__ void ld_nc_v8(const float* p, float v[8]) {
    asm volatile("ld.global.nc.v8.f32 {%0,%1,%2,%3,%4,%5,%6,%7}, [%8];"
                 : "=f"(v[0]), "=f"(v[1]), "=f"(v[2]), "=f"(v[3]),
                   "=f"(v[4]), "=f"(v[5]), "=f"(v[6]), "=f"(v[7])
                 : "l"(p));
}

__device__ __forceinline__ void st_cs_v8(float* p, const float v[8]) {
    asm volatile("st.global.cs.v8.f32 [%0], {%1,%2,%3,%4,%5,%6,%7,%8};"
                 :: "l"(p),
                    "f"(v[0]), "f"(v[1]), "f"(v[2]), "f"(v[3]),
                    "f"(v[4]), "f"(v[5]), "f"(v[6]), "f"(v[7])
                 : "memory");
}

__global__ __launch_bounds__(128, 12)
void relu_conv_kernel(
    const float* __restrict__ lx, const float* __restrict__ ux,
    const float* __restrict__ lc, const float* __restrict__ uc,
    const float* __restrict__ xmin, const float* __restrict__ xmax,
    float* __restrict__ lx_out, float* __restrict__ ux_out,
    float* __restrict__ lc_out, float* __restrict__ uc_out)
{
    const int tid = threadIdx.x;                       // 0..127
    const int n   = blockIdx.x;                        // this block's neuron
    const size_t base = (size_t)n * 1024 + (size_t)tid * 8;

    // Front batch: two 256-bit streaming loads (32B-aligned).
    float vlx[8], vux[8];
    ld_cs_v8(lx + base, vlx);
    ld_cs_v8(ux + base, vux);
    const float lcv = __ldg(lc + n);
    const float ucv = __ldg(uc + n);

    // Broadcast bounds (8 KB total, L1/L2 resident after wave 1).
    float vmn[8], vmx[8];
    ld_nc_v8(xmin + (size_t)tid * 8, vmn);
    ld_nc_v8(xmax + (size_t)tid * 8, vmx);

    // Accumulate. (l>0 ? mn : (l<0 ? mx : 0)) * l == (l>0 ? mn : mx) * l
    // for finite bounds (the l==0 branch multiplies to zero either way).
    float sl = 0.f, su = 0.f;
    #pragma unroll
    for (int i = 0; i < 8; i++) {
        sl += (vlx[i] > 0.f ? vmn[i] : vmx[i]) * vlx[i];
        su += (vux[i] > 0.f ? vmx[i] : vmn[i]) * vux[i];
    }

    // Warp reduction.
    #pragma unroll
    for (int off = 16; off; off >>= 1) {
        sl += __shfl_down_sync(0xffffffffu, sl, off);
        su += __shfl_down_sync(0xffffffffu, su, off);
    }

    __shared__ float2 sPart[4];                        // per-warp partials
    const int warp = tid >> 5, lane = tid & 31;
    if (lane == 0) sPart[warp] = make_float2(sl, su);
    __syncthreads();                                   // the ONLY barrier

    // Every thread redundantly finalizes (broadcast smem reads).
    const float2 p0 = sPart[0], p1 = sPart[1], p2 = sPart[2], p3 = sPart[3];
    const float l = (p0.x + p1.x) + (p2.x + p3.x) + lcv;
    const float u = (p0.y + p1.y) + (p2.y + p3.y) + ucv;

    const bool alive = (l >= 0.f);
    const bool cross = (l < 0.f) && (u > 0.f);
    float slope = cross ? (u / (u - l)) : 1.f;
    slope = fminf(fmaxf(slope, 0.f), 1.f);

    // Per-neuron epilogue multipliers (identical values to the reference
    // selects; 0*finite stores +/-0 which is exact under rel-err).
    const float mlx = alive ? 1.f : 0.f;
    const float mux = alive ? 1.f : (cross ? slope : 0.f);

    if (tid == 0) {
        lc_out[n] = alive ? lcv : 0.f;
        uc_out[n] = alive ? ucv : (cross ? (slope * ucv - slope * l) : 0.f);
    }

    float olx[8], oux[8];
    #pragma unroll
    for (int i = 0; i < 8; i++) {
        olx[i] = mlx * vlx[i];
        oux[i] = mux * vux[i];
    }
    st_cs_v8(lx_out + base, olx);
    st_cs_v8(ux_out + base, oux);
}

extern "C" void kernel_launch(void* const* d_in, const int* in_sizes, int n_in,
                              void* d_out, int out_size)
{
    const float* lx   = (const float*)d_in[0];
    const float* ux   = (const float*)d_in[1];
    const float* lc   = (const float*)d_in[2];
    const float* uc   = (const float*)d_in[3];
    const float* xmin = (const float*)d_in[4];
    const float* xmax = (const float*)d_in[5];

    const int neurons = in_sizes[2];          // C*H*W = 32768
    const size_t nel  = (size_t)neurons * 1024;

    float* out    = (float*)d_out;
    float* lx_out = out;
    float* ux_out = out + nel;
    float* lc_out = out + 2 * nel;
    float* uc_out = out + 2 * nel + neurons;

    relu_conv_kernel<<<neurons, 128>>>(lx, ux, lc, uc, xmin, xmax,
                                       lx_out, ux_out, lc_out, uc_out);
}

// round 16
// speedup vs baseline: 1.0496x; 1.0027x over previous
#include <cuda_runtime.h>

// ReLU_Conv (CROWN-style ReLU relaxation over bound maps) — FINAL
// Measured optimum over 15 GB300 rounds (reproduced twice: ncu 75.5/75.9us,
// DRAM 80.3/80.5%):
//   1 neuron per 128-thread block; Blackwell 256-bit vector memory ops
//   (LDG.E.256 / STG.E.256): each thread owns 8 consecutive floats of the
//   row -> 2-instruction front batch of streaming loads, 2 vector stores.
//   occ 12 / 40-reg allocator mode (occ>=13 spills: DRAM -> 75.8%),
//   single 4-warp barrier, redundant per-thread finalize.
//   ~6.38 TB/s (80% of spec HBM) = architectural ceiling for this fused
//   1:1 read/write stream; MLP 2/8/16, occ 22-97%, persistence, prefetch,
//   and warp-per-neuron all measured worse.
// Output layout: [lx_out | ux_out | lc_out | uc_out]

__device__ __forceinline__ void ld_cs_v8(const float* p, float v[8]) {
    asm volatile("ld.global.cs.v8.f32 {%0,%1,%2,%3,%4,%5,%6,%7}, [%8];"
                 : "=f"(v[0]), "=f"(v[1]), "=f"(v[2]), "=f"(v[3]),
                   "=f"(v[4]), "=f"(v[5]), "=f"(v[6]), "=f"(v[7])
                 : "l"(p));
}

__device__ __forceinline__ void ld_nc_v8(const float* p, float v[8]) {
    asm volatile("ld.global.nc.v8.f32 {%0,%1,%2,%3,%4,%5,%6,%7}, [%8];"
                 : "=f"(v[0]), "=f"(v[1]), "=f"(v[2]), "=f"(v[3]),
                   "=f"(v[4]), "=f"(v[5]), "=f"(v[6]), "=f"(v[7])
                 : "l"(p));
}

__device__ __forceinline__ void st_cs_v8(float* p, const float v[8]) {
    asm volatile("st.global.cs.v8.f32 [%0], {%1,%2,%3,%4,%5,%6,%7,%8};"
                 :: "l"(p),
                    "f"(v[0]), "f"(v[1]), "f"(v[2]), "f"(v[3]),
                    "f"(v[4]), "f"(v[5]), "f"(v[6]), "f"(v[7])
                 : "memory");
}

__global__ __launch_bounds__(128, 12)
void relu_conv_kernel(
    const float* __restrict__ lx, const float* __restrict__ ux,
    const float* __restrict__ lc, const float* __restrict__ uc,
    const float* __restrict__ xmin, const float* __restrict__ xmax,
    float* __restrict__ lx_out, float* __restrict__ ux_out,
    float* __restrict__ lc_out, float* __restrict__ uc_out)
{
    const int tid = threadIdx.x;                       // 0..127
    const int n   = blockIdx.x;                        // this block's neuron
    const size_t base = (size_t)n * 1024 + (size_t)tid * 8;

    // Front batch: two 256-bit streaming loads (32B-aligned).
    float vlx[8], vux[8];
    ld_cs_v8(lx + base, vlx);
    ld_cs_v8(ux + base, vux);
    const float lcv = __ldg(lc + n);
    const float ucv = __ldg(uc + n);

    // Broadcast bounds (8 KB total, L1/L2 resident after wave 1).
    float vmn[8], vmx[8];
    ld_nc_v8(xmin + (size_t)tid * 8, vmn);
    ld_nc_v8(xmax + (size_t)tid * 8, vmx);

    // Accumulate. (l>0 ? mn : (l<0 ? mx : 0)) * l == (l>0 ? mn : mx) * l
    // for finite bounds (the l==0 branch multiplies to zero either way).
    float sl = 0.f, su = 0.f;
    #pragma unroll
    for (int i = 0; i < 8; i++) {
        sl += (vlx[i] > 0.f ? vmn[i] : vmx[i]) * vlx[i];
        su += (vux[i] > 0.f ? vmx[i] : vmn[i]) * vux[i];
    }

    // Warp reduction.
    #pragma unroll
    for (int off = 16; off; off >>= 1) {
        sl += __shfl_down_sync(0xffffffffu, sl, off);
        su += __shfl_down_sync(0xffffffffu, su, off);
    }

    __shared__ float2 sPart[4];                        // per-warp partials
    const int warp = tid >> 5, lane = tid & 31;
    if (lane == 0) sPart[warp] = make_float2(sl, su);
    __syncthreads();                                   // the ONLY barrier

    // Every thread redundantly finalizes (broadcast smem reads).
    const float2 p0 = sPart[0], p1 = sPart[1], p2 = sPart[2], p3 = sPart[3];
    const float l = (p0.x + p1.x) + (p2.x + p3.x) + lcv;
    const float u = (p0.y + p1.y) + (p2.y + p3.y) + ucv;

    const bool alive = (l >= 0.f);
    const bool cross = (l < 0.f) && (u > 0.f);
    float slope = cross ? (u / (u - l)) : 1.f;
    slope = fminf(fmaxf(slope, 0.f), 1.f);

    // Per-neuron epilogue multipliers (identical values to the reference
    // selects; 0*finite stores +/-0 which is exact under rel-err).
    const float mlx = alive ? 1.f : 0.f;
    const float mux = alive ? 1.f : (cross ? slope : 0.f);

    if (tid == 0) {
        lc_out[n] = alive ? lcv : 0.f;
        uc_out[n] = alive ? ucv : (cross ? (slope * ucv - slope * l) : 0.f);
    }

    float olx[8], oux[8];
    #pragma unroll
    for (int i = 0; i < 8; i++) {
        olx[i] = mlx * vlx[i];
        oux[i] = mux * vux[i];
    }
    st_cs_v8(lx_out + base, olx);
    st_cs_v8(ux_out + base, oux);
}

extern "C" void kernel_launch(void* const* d_in, const int* in_sizes, int n_in,
                              void* d_out, int out_size)
{
    const float* lx   = (const float*)d_in[0];
    const float* ux   = (const float*)d_in[1];
    const float* lc   = (const float*)d_in[2];
    const float* uc   = (const float*)d_in[3];
    const float* xmin = (const float*)d_in[4];
    const float* xmax = (const float*)d_in[5];

    const int neurons = in_sizes[2];          // C*H*W = 32768
    const size_t nel  = (size_t)neurons * 1024;

    float* out    = (float*)d_out;
    float* lx_out = out;
    float* ux_out = out + nel;
    float* lc_out = out + 2 * nel;
    float* uc_out = out + 2 * nel + neurons;

    relu_conv_kernel<<<neurons, 128>>>(lx, ux, lc, uc, xmin, xmax,
                                       lx_out, ux_out, lc_out, uc_out);
}